// round 6
// baseline (speedup 1.0000x reference)
#include <cuda_runtime.h>
#include <math.h>

#define NB    8
#define D_IN  514
#define T_IN  4000
#define T_OUT 3999
#define NC    19                 // 16 output cols + 3 halo cols per block
#define AS    (256 * NC + 16)    // plane stride: Ai base ends up == 16 (mod 32) banks

// dynamic smem layout (floats):
//   Ar   [AS]          re plane, row stride NC
//   Ai   [AS]          im plane
//   stw  [256] float2  e^{+2pi i e/256}
//   outs [16*257]      staged output tile
#define SMEM_FLOATS (2 * AS + 512 + 16 * 257)
#define SMEM_BYTES  (SMEM_FLOATS * 4)

__device__ __forceinline__ int rev4(int q) {   // reverse 4 base-4 digits (involution)
    return ((q & 3) << 6) | (((q >> 2) & 3) << 4) | (((q >> 4) & 3) << 2) | (q >> 6);
}

// ---------------------------------------------------------------------------
// Fused: build conj-sym pack G -> 256-pt radix-4 DIF FFT (e+ kernel) ->
// windowed 4-frame overlap-add + flip + transpose, all in one block.
// Block: 256 threads, 19 FFT columns, 16 output columns. Grid (250, 8).
// ---------------------------------------------------------------------------
__global__ __launch_bounds__(256) void fused_kernel(const float* __restrict__ in,
                                                    const float* __restrict__ win,
                                                    float* __restrict__ out) {
    extern __shared__ float smem[];
    float*  Ar   = smem;
    float*  Ai   = smem + AS;
    float2* stw  = (float2*)(smem + 2 * AS);
    float*  outs = smem + 2 * AS + 512;

    const int tid = threadIdx.x;
    const int b   = blockIdx.y;
    const int t0  = blockIdx.x * 16;
    const float* base = in + (size_t)b * D_IN * T_IN;

    // Twiddles e^{+2pi i e / 256}
    stw[tid] = make_float2(cospif(tid / 128.0f), sinpif(tid / 128.0f));

    // ---- Build G[k] for 19 columns (zero for gt < 0 at the left boundary) ----
    for (int idx = tid; idx < 129 * NC; idx += 256) {
        int kp = idx / NC;
        int c  = idx - kp * NC;
        int gt = t0 - 3 + c;
        bool v = (gt >= 0);
        const float* col = base + gt;          // only deref if v
        if (kp == 0) {
            float r0 = v ? col[0] : 0.0f;
            Ar[c] = r0;
            Ai[c] = r0;
        } else if (kp == 128) {
            float r = v ? col[(size_t)128 * T_IN] : 0.0f;
            float m = v ? col[(size_t)385 * T_IN] : 0.0f;   // 257+128
            Ar[128 * NC + c] = 2.0f * r;
            Ai[128 * NC + c] = 2.0f * m;
        } else {
            float rk = 0.0f, mk = 0.0f, rp = 0.0f, mp = 0.0f;
            if (v) {
                rk = col[(size_t)kp * T_IN];
                mk = col[(size_t)(257 + kp) * T_IN];
                rp = col[(size_t)(256 - kp) * T_IN];
                mp = col[(size_t)(513 - kp) * T_IN];
            }
            float Er = rk + rp, Ei = mp - mk;
            float Dr = rk - rp, Di = -(mk + mp);
            float wr = cospif(kp / 256.0f), wi = sinpif(kp / 256.0f);
            float Or = Dr * wr - Di * wi;
            float Oi = Dr * wi + Di * wr;
            Ar[kp * NC + c]         = Er - Oi;
            Ai[kp * NC + c]         = Ei + Or;
            Ar[(256 - kp) * NC + c] = Er + Oi;
            Ai[(256 - kp) * NC + c] = Or - Ei;
        }
    }
    __syncthreads();

    // ---- 4 radix-4 DIF stages, in place ----
#pragma unroll
    for (int s = 0; s < 4; s++) {
        const int m  = 64 >> (2 * s);
        const int L  = 1 << (2 * s);
        const int lg = 6 - 2 * s;
        for (int idx = tid; idx < 64 * NC; idx += 256) {
            int c  = idx >> 6;               // 0..18
            int i4 = idx & 63;
            int i   = i4 & (m - 1);
            int sub = i4 >> lg;
            int p0  = ((sub << (lg + 2)) + i) * NC + c;
            int p1  = p0 + m * NC;
            int p2  = p0 + 2 * m * NC;
            int p3  = p0 + 3 * m * NC;
            float x0r = Ar[p0], x0i = Ai[p0];
            float x1r = Ar[p1], x1i = Ai[p1];
            float x2r = Ar[p2], x2i = Ai[p2];
            float x3r = Ar[p3], x3i = Ai[p3];
            float t0r = x0r + x2r, t0i = x0i + x2i;
            float t1r = x0r - x2r, t1i = x0i - x2i;
            float t2r = x1r + x3r, t2i = x1i + x3i;
            float t3r = x1r - x3r, t3i = x1i - x3i;
            float u0r = t0r + t2r, u0i = t0i + t2i;
            float u2r = t0r - t2r, u2i = t0i - t2i;
            float u1r = t1r - t3i, u1i = t1i + t3r;    // t1 + i*t3
            float u3r = t1r + t3i, u3i = t1i - t3r;    // t1 - i*t3
            int e = i * L;
            float2 w1 = stw[e];
            float2 w2 = stw[2 * e];
            float2 w3 = stw[3 * e];
            Ar[p0] = u0r;                 Ai[p0] = u0i;
            Ar[p1] = u1r * w1.x - u1i * w1.y;  Ai[p1] = u1r * w1.y + u1i * w1.x;
            Ar[p2] = u2r * w2.x - u2i * w2.y;  Ai[p2] = u2r * w2.y + u2i * w2.x;
            Ar[p3] = u3r * w3.x - u3i * w3.y;  Ai[p3] = u3r * w3.y + u3i * w3.x;
        }
        __syncthreads();
    }

    // Position p holds z[q], q = rev4(p); s[2q] = Re z[q] (Ar), s[2q+1] = Im (Ai).
    // ---- Epilogue: out[b,t,j] = 256*( win[1023-j]*S[511-j][t]
    //        + win[767-j]*S[255-j][t-1] + win[511-j]*S[511-j][t-2]
    //        + win[255-j]*S[255-j][t-3] ),  col(t0+dt) = dt+3.
    // Warp = 16 dt-lanes x 2 adjacent j (same rev-row, opposite plane). ----
    {
        const int wid  = tid >> 5;
        const int half = (tid >> 4) & 1;
        const int dt   = tid & 15;
#pragma unroll
        for (int P = 0; P < 16; P++) {
            int j  = P * 16 + wid * 2 + half;
            int n1 = 511 - j;
            int n2 = 255 - j;
            const float* pl = (n1 & 1) ? Ai : Ar;      // n1, n2 share parity
            int r1 = rev4(n1 >> 1) * NC;
            int r2 = rev4(n2 >> 1) * NC;
            float w1 = 256.0f * __ldg(&win[1023 - j]);
            float w2 = 256.0f * __ldg(&win[767 - j]);
            float w3 = 256.0f * __ldg(&win[511 - j]);
            float w4 = 256.0f * __ldg(&win[255 - j]);
            float v = w1 * pl[r1 + dt + 3]
                    + w2 * pl[r2 + dt + 2]
                    + w3 * pl[r1 + dt + 1]
                    + w4 * pl[r2 + dt];
            outs[dt * 257 + j] = v;
        }
    }
    __syncthreads();

    // ---- Coalesced copy to global ----
    {
        float* ob = out + ((size_t)b * T_OUT + t0) * 256 + tid;
#pragma unroll
        for (int dt = 0; dt < 16; dt++) {
            if (t0 + dt >= T_OUT) break;
            ob[(size_t)dt * 256] = outs[dt * 257 + tid];
        }
    }
}

// ---------------------------------------------------------------------------
extern "C" void kernel_launch(void* const* d_in, const int* in_sizes, int n_in,
                              void* d_out, int out_size) {
    const float* in  = (const float*)d_in[0];   // (8, 514, 4000) f32
    const float* win = (const float*)d_in[1];   // (1024,) f32
    float* out = (float*)d_out;                 // (8, 3999*256) f32

    cudaFuncSetAttribute(fused_kernel,
                         cudaFuncAttributeMaxDynamicSharedMemorySize, SMEM_BYTES);

    dim3 g(250, NB);                            // 250 t-tiles x 8 batches
    fused_kernel<<<g, 256, SMEM_BYTES>>>(in, win, out);
}

// round 7
// speedup vs baseline: 1.5760x; 1.5760x over previous
#include <cuda_runtime.h>
#include <math.h>

#define NB    8
#define D_IN  514
#define T_IN  4000
#define T_OUT 3999

// Scratch: S2[b][q][t] = (s[2q], s[2q+1]),  q = 0..255
__device__ float2 g_S2[(size_t)NB * 256 * T_IN];   // 65.5 MB

__device__ __forceinline__ int rev4(int q) {   // reverse 4 base-4 digits
    return ((q & 3) << 6) | (((q >> 2) & 3) << 4) | (((q >> 4) & 3) << 2) | (q >> 6);
}

// ---------------------------------------------------------------------------
// Inverse real FFT per column via 256-pt complex DFT (e^{+} kernel).
// Block: 16 columns, 256 threads = 16 c-lanes x 16 k-lanes.
// z = DFT256(G) radix-4 DIF in-place; position p holds z[rev4(p)].
// Scatter as float2: S2[q][t] = z[q] = (s[2q], s[2q+1]).
// ---------------------------------------------------------------------------
__global__ __launch_bounds__(256) void fft_kernel(const float* __restrict__ in) {
    __shared__ float2 A[256][17];    // [k][c], pad 17
    __shared__ float2 stw[256];      // e^{+2pi i e/256}
    __shared__ float2 stw2[128];     // e^{+pi i k/256}

    const int tid = threadIdx.x;
    const int c   = tid & 15;
    const int lk  = tid >> 4;                 // 0..15
    const int gc0 = blockIdx.x * 16;
    const int b   = gc0 / T_IN;               // 16 | 4000 -> never straddles b
    const int t0  = gc0 - b * T_IN;
    const float* base = in + (size_t)b * D_IN * T_IN + t0;

    stw[tid] = make_float2(cospif(tid / 128.0f), sinpif(tid / 128.0f));
    if (tid < 128)
        stw2[tid] = make_float2(cospif(tid / 256.0f), sinpif(tid / 256.0f));
    __syncthreads();

    // ---- Build G[k] (natural order) ----
#pragma unroll
    for (int it = 0; it < 9; it++) {
        int kp = lk + 16 * it;
        if (kp > 128) break;
        if (kp == 0) {
            float r0 = base[c];
            A[0][c] = make_float2(r0, r0);
        } else if (kp == 128) {
            float r = base[(size_t)128 * T_IN + c];
            float m = base[(size_t)385 * T_IN + c];     // 257+128
            A[128][c] = make_float2(2.0f * r, 2.0f * m);
        } else {
            float rk = base[(size_t)kp * T_IN + c];
            float mk = base[(size_t)(257 + kp) * T_IN + c];
            float rp = base[(size_t)(256 - kp) * T_IN + c];
            float mp = base[(size_t)(513 - kp) * T_IN + c];
            float Er = rk + rp, Ei = mp - mk;
            float Dr = rk - rp, Di = -(mk + mp);
            float2 w = stw2[kp];
            float Or = Dr * w.x - Di * w.y;
            float Oi = Dr * w.y + Di * w.x;
            A[kp][c]       = make_float2(Er - Oi, Ei + Or);
            A[256 - kp][c] = make_float2(Er + Oi, Or - Ei);
        }
    }
    __syncthreads();

    // ---- 4 radix-4 DIF stages (in-place) ----
#pragma unroll
    for (int s = 0; s < 4; s++) {
        const int m  = 64 >> (2 * s);
        const int L  = 1 << (2 * s);
        const int lg = 6 - 2 * s;
#pragma unroll
        for (int it = 0; it < 4; it++) {
            int i4  = lk + 16 * it;           // 0..63
            int i   = i4 & (m - 1);
            int sub = i4 >> lg;
            int p0  = (sub << (lg + 2)) + i;
            float2 x0 = A[p0][c];
            float2 x1 = A[p0 + m][c];
            float2 x2 = A[p0 + 2 * m][c];
            float2 x3 = A[p0 + 3 * m][c];
            float t0r = x0.x + x2.x, t0i = x0.y + x2.y;
            float t1r = x0.x - x2.x, t1i = x0.y - x2.y;
            float t2r = x1.x + x3.x, t2i = x1.y + x3.y;
            float t3r = x1.x - x3.x, t3i = x1.y - x3.y;
            float u0r = t0r + t2r, u0i = t0i + t2i;
            float u2r = t0r - t2r, u2i = t0i - t2i;
            float u1r = t1r - t3i, u1i = t1i + t3r;    // t1 + i*t3
            float u3r = t1r + t3i, u3i = t1i - t3r;    // t1 - i*t3
            int e = i * L;
            float2 w1 = stw[e];
            float2 w2 = stw[2 * e];
            float2 w3 = stw[3 * e];
            A[p0][c]         = make_float2(u0r, u0i);
            A[p0 + m][c]     = make_float2(u1r * w1.x - u1i * w1.y,
                                           u1r * w1.y + u1i * w1.x);
            A[p0 + 2 * m][c] = make_float2(u2r * w2.x - u2i * w2.y,
                                           u2r * w2.y + u2i * w2.x);
            A[p0 + 3 * m][c] = make_float2(u3r * w3.x - u3i * w3.y,
                                           u3r * w3.y + u3i * w3.x);
        }
        __syncthreads();
    }

    // ---- Scatter: one float2 store per point ----
    float2* S2b = g_S2 + (size_t)b * 256 * T_IN + t0;
#pragma unroll
    for (int it = 0; it < 16; it++) {
        int p = lk + 16 * it;
        int q = rev4(p);
        S2b[(size_t)q * T_IN + c] = A[p][c];
    }
}

// ---------------------------------------------------------------------------
// Epilogue: out[b,t,j] = 256*( win[1023-j]*S[511-j][t] + win[767-j]*S[255-j][t-1]
//                            + win[511-j]*S[511-j][t-2]+ win[255-j]*S[255-j][t-3] )
// S[n] = component (n&1) of S2[n>>1]. Rows 511-j -> q1 family, 255-j -> q2.
// Block: t-tile 32 x j-half 128 x b; 256 thr = 128 j x 2 t-subtiles.
// ---------------------------------------------------------------------------
__global__ __launch_bounds__(256) void epilogue_kernel(const float* __restrict__ win,
                                                       float* __restrict__ out) {
    __shared__ float2 sQ1[64][35];   // q1 family rows
    __shared__ float2 sQ2[64][35];   // q2 family rows

    const int t0 = blockIdx.x * 32;
    const int jh = blockIdx.y;            // 0 or 1
    const int b  = blockIdx.z;
    const int j0 = jh * 128;
    const int q2base = 64 * (1 - jh);
    const int q1base = 128 + q2base;
    const int tid = threadIdx.x;

    const float2* Sb = g_S2 + (size_t)b * 256 * T_IN;

    for (int idx = tid; idx < 64 * 35; idx += 256) {
        int rr = idx / 35;
        int tc = idx - rr * 35;
        int ts = t0 - 3 + tc;
        float2 v1 = make_float2(0.0f, 0.0f);
        float2 v2 = v1;
        if (ts >= 0) {
            v1 = Sb[(size_t)(q1base + rr) * T_IN + ts];
            v2 = Sb[(size_t)(q2base + rr) * T_IN + ts];
        }
        sQ1[rr][tc] = v1;
        sQ2[rr][tc] = v2;
    }
    __syncthreads();

    const int jt = tid & 127;
    const int th = tid >> 7;
    const int j  = j0 + jt;
    const int n1 = 511 - j;               // n2 = 255-j has same parity
    const int lr1 = (n1 >> 1) - q1base;
    const int lr2 = ((255 - j) >> 1) - q2base;
    const int comp = n1 & 1;
    const float* p1 = &sQ1[lr1][0].x + comp;   // stride 2 floats per tc
    const float* p2 = &sQ2[lr2][0].x + comp;

    const float w1 = 256.0f * __ldg(&win[1023 - j]);
    const float w2 = 256.0f * __ldg(&win[767 - j]);
    const float w3 = 256.0f * __ldg(&win[511 - j]);
    const float w4 = 256.0f * __ldg(&win[255 - j]);

    const int dt0 = th * 16;
    float* ob = out + ((size_t)b * T_OUT + t0) * 256 + j;
#pragma unroll
    for (int q = 0; q < 16; q++) {
        int dt = dt0 + q;
        if (t0 + dt >= T_OUT) break;
        float v = w1 * p1[(dt + 3) * 2]
                + w2 * p2[(dt + 2) * 2]
                + w3 * p1[(dt + 1) * 2]
                + w4 * p2[dt * 2];
        ob[(size_t)dt * 256] = v;
    }
}

// ---------------------------------------------------------------------------
extern "C" void kernel_launch(void* const* d_in, const int* in_sizes, int n_in,
                              void* d_out, int out_size) {
    const float* in  = (const float*)d_in[0];   // (8, 514, 4000) f32
    const float* win = (const float*)d_in[1];   // (1024,) f32
    float* out = (float*)d_out;                 // (8, 3999*256) f32

    fft_kernel<<<2000, 256>>>(in);              // 16 columns per block

    dim3 gE(125, 2, NB);
    epilogue_kernel<<<gE, 256>>>(win, out);
}

// round 8
// speedup vs baseline: 1.6584x; 1.0523x over previous
#include <cuda_runtime.h>
#include <math.h>

#define NB    8
#define D_IN  514
#define T_IN  4000
#define T_OUT 3999
#define RS    17                // smem row stride (floats), odd => conflict-free

// Scratch: S2[b][q][t] = (s[2q], s[2q+1]),  q = 0..255
__device__ float2 g_S2[(size_t)NB * 256 * T_IN];   // 65.5 MB

// ---------------------------------------------------------------------------
// 16-pt complex DFT, e^{+} kernel, in place, radix-4 x 2 with compile-time
// W16 twiddles (local const arrays fold to immediates under full unroll).
// ---------------------------------------------------------------------------
__device__ __forceinline__ void dft16(float* xr, float* xi) {
    const float W16R[16] = { 1.0f,  0.923879533f,  0.707106781f,  0.382683432f,
                             0.0f, -0.382683432f, -0.707106781f, -0.923879533f,
                            -1.0f, -0.923879533f, -0.707106781f, -0.382683432f,
                             0.0f,  0.382683432f,  0.707106781f,  0.923879533f };
    const float W16I[16] = { 0.0f,  0.382683432f,  0.707106781f,  0.923879533f,
                             1.0f,  0.923879533f,  0.707106781f,  0.382683432f,
                             0.0f, -0.382683432f, -0.707106781f, -0.923879533f,
                            -1.0f, -0.923879533f, -0.707106781f, -0.382683432f };
    float qr[16], qi[16];
    // Stage A: 4-pt e+ DFT over a of x[4a+b], then q[4j+b] = P[b][j]*W16^{bj}
#pragma unroll
    for (int b = 0; b < 4; b++) {
        float a0r = xr[b],      a0i = xi[b];
        float a1r = xr[b + 4],  a1i = xi[b + 4];
        float a2r = xr[b + 8],  a2i = xi[b + 8];
        float a3r = xr[b + 12], a3i = xi[b + 12];
        float t0r = a0r + a2r, t0i = a0i + a2i;
        float t1r = a0r - a2r, t1i = a0i - a2i;
        float t2r = a1r + a3r, t2i = a1i + a3i;
        float t3r = a1r - a3r, t3i = a1i - a3i;
        float p0r = t0r + t2r, p0i = t0i + t2i;
        float p1r = t1r - t3i, p1i = t1i + t3r;   // + i*t3
        float p2r = t0r - t2r, p2i = t0i - t2i;
        float p3r = t1r + t3i, p3i = t1i - t3r;   // - i*t3
        qr[b]      = p0r;  qi[b]      = p0i;
#pragma unroll
        for (int j = 1; j < 4; j++) {
            float pr = (j == 1) ? p1r : (j == 2) ? p2r : p3r;
            float pi = (j == 1) ? p1i : (j == 2) ? p2i : p3i;
            float wr = W16R[(b * j) & 15], wi = W16I[(b * j) & 15];
            qr[4 * j + b] = pr * wr - pi * wi;
            qi[4 * j + b] = pr * wi + pi * wr;
        }
    }
    // Stage B: 4-pt e+ DFT over b of q[4j+b] -> F[j+4m]
#pragma unroll
    for (int j = 0; j < 4; j++) {
        float b0r = qr[4 * j],     b0i = qi[4 * j];
        float b1r = qr[4 * j + 1], b1i = qi[4 * j + 1];
        float b2r = qr[4 * j + 2], b2i = qi[4 * j + 2];
        float b3r = qr[4 * j + 3], b3i = qi[4 * j + 3];
        float t0r = b0r + b2r, t0i = b0i + b2i;
        float t1r = b0r - b2r, t1i = b0i - b2i;
        float t2r = b1r + b3r, t2i = b1i + b3i;
        float t3r = b1r - b3r, t3i = b1i - b3i;
        xr[j]      = t0r + t2r;  xi[j]      = t0i + t2i;
        xr[j + 4]  = t1r - t3i;  xi[j + 4]  = t1i + t3r;
        xr[j + 8]  = t0r - t2r;  xi[j + 8]  = t0i - t2i;
        xr[j + 12] = t1r + t3i;  xi[j + 12] = t1i - t3r;
    }
}

// ---------------------------------------------------------------------------
// Inverse real FFT, 256-pt complex DFT (e+) as 16x16 Cooley-Tukey.
// Block: 16 columns x 16 k-lanes = 256 threads. One smem exchange.
// ---------------------------------------------------------------------------
__global__ __launch_bounds__(256, 3) void fft_kernel(const float* __restrict__ in) {
    __shared__ float Ar[256 * RS];
    __shared__ float Ai[256 * RS];

    const int tid = threadIdx.x;
    const int c   = tid & 15;
    const int lk  = tid >> 4;                 // n2 in phase 1, k1 in phase 2
    const int gc0 = blockIdx.x * 16;
    const int b   = gc0 / T_IN;               // 16 | 4000 -> never straddles b
    const int t0  = gc0 - b * T_IN;
    const float* base = in + (size_t)b * D_IN * T_IN + t0;

    // ---- Build G[k] (natural order) into smem planes ----
#pragma unroll
    for (int it = 0; it < 9; it++) {
        int idx = tid + it * 256;
        if (idx >= 129 * 16) break;
        int kp = idx >> 4;
        int cc = idx & 15;
        if (kp == 0) {
            float r0 = base[cc];
            Ar[cc] = r0;
            Ai[cc] = r0;
        } else if (kp == 128) {
            float r = base[(size_t)128 * T_IN + cc];
            float m = base[(size_t)385 * T_IN + cc];     // 257+128
            Ar[128 * RS + cc] = 2.0f * r;
            Ai[128 * RS + cc] = 2.0f * m;
        } else {
            float rk = base[(size_t)kp * T_IN + cc];
            float mk = base[(size_t)(257 + kp) * T_IN + cc];
            float rp = base[(size_t)(256 - kp) * T_IN + cc];
            float mp = base[(size_t)(513 - kp) * T_IN + cc];
            float Er = rk + rp, Ei = mp - mk;
            float Dr = rk - rp, Di = -(mk + mp);
            float wr = cospif(kp / 256.0f), wi = sinpif(kp / 256.0f);
            float Or = Dr * wr - Di * wi;
            float Oi = Dr * wi + Di * wr;
            Ar[kp * RS + cc]         = Er - Oi;
            Ai[kp * RS + cc]         = Ei + Or;
            Ar[(256 - kp) * RS + cc] = Er + Oi;
            Ai[(256 - kp) * RS + cc] = Or - Ei;
        }
    }
    __syncthreads();

    float xr[16], xi[16];

    // ---- Phase 1: thread (c, n2=lk): X[a] = G[16a + n2], 16-pt DFT over a ----
#pragma unroll
    for (int a = 0; a < 16; a++) {
        int r = (16 * a + lk) * RS + c;
        xr[a] = Ar[r];
        xi[a] = Ai[r];
    }
    dft16(xr, xi);

    // ---- Mid twiddle: F[k1] *= W256^{+n2*k1} (cumulative complex powers) ----
    {
        float bwr = cospif(lk / 128.0f), bwi = sinpif(lk / 128.0f);
        float wr = bwr, wi = bwi;
#pragma unroll
        for (int k1 = 1; k1 < 16; k1++) {
            float fr = xr[k1], fi = xi[k1];
            xr[k1] = fr * wr - fi * wi;
            xi[k1] = fr * wi + fi * wr;
            float nwr = wr * bwr - wi * bwi;
            float nwi = wr * bwi + wi * bwr;
            wr = nwr; wi = nwi;
        }
    }
    __syncthreads();    // everyone's loads done before overwrite

    // ---- Exchange: H[n2][k1] stored at row 16*k1 + n2 ----
#pragma unroll
    for (int k1 = 0; k1 < 16; k1++) {
        int r = (16 * k1 + lk) * RS + c;
        Ar[r] = xr[k1];
        Ai[r] = xi[k1];
    }
    __syncthreads();

    // ---- Phase 2: thread (c, k1=lk): Y[n2] = H[n2][k1], 16-pt DFT over n2 ----
#pragma unroll
    for (int n2 = 0; n2 < 16; n2++) {
        int r = (16 * lk + n2) * RS + c;
        xr[n2] = Ar[r];
        xi[n2] = Ai[r];
    }
    dft16(xr, xi);

    // ---- Scatter: z[k1 + 16*k2], natural order, one float2 per point ----
    float2* S2b = g_S2 + (size_t)b * 256 * T_IN + t0;
#pragma unroll
    for (int k2 = 0; k2 < 16; k2++) {
        S2b[(size_t)(lk + 16 * k2) * T_IN + c] = make_float2(xr[k2], xi[k2]);
    }
}

// ---------------------------------------------------------------------------
// Epilogue (unchanged — measured 27.8us):
// out[b,t,j] = 256*( win[1023-j]*S[511-j][t] + win[767-j]*S[255-j][t-1]
//                  + win[511-j]*S[511-j][t-2]+ win[255-j]*S[255-j][t-3] )
// S[n] = component (n&1) of S2[n>>1].
// ---------------------------------------------------------------------------
__global__ __launch_bounds__(256) void epilogue_kernel(const float* __restrict__ win,
                                                       float* __restrict__ out) {
    __shared__ float2 sQ1[64][35];
    __shared__ float2 sQ2[64][35];

    const int t0 = blockIdx.x * 32;
    const int jh = blockIdx.y;
    const int b  = blockIdx.z;
    const int j0 = jh * 128;
    const int q2base = 64 * (1 - jh);
    const int q1base = 128 + q2base;
    const int tid = threadIdx.x;

    const float2* Sb = g_S2 + (size_t)b * 256 * T_IN;

    for (int idx = tid; idx < 64 * 35; idx += 256) {
        int rr = idx / 35;
        int tc = idx - rr * 35;
        int ts = t0 - 3 + tc;
        float2 v1 = make_float2(0.0f, 0.0f);
        float2 v2 = v1;
        if (ts >= 0) {
            v1 = Sb[(size_t)(q1base + rr) * T_IN + ts];
            v2 = Sb[(size_t)(q2base + rr) * T_IN + ts];
        }
        sQ1[rr][tc] = v1;
        sQ2[rr][tc] = v2;
    }
    __syncthreads();

    const int jt = tid & 127;
    const int th = tid >> 7;
    const int j  = j0 + jt;
    const int n1 = 511 - j;
    const int lr1 = (n1 >> 1) - q1base;
    const int lr2 = ((255 - j) >> 1) - q2base;
    const int comp = n1 & 1;
    const float* p1 = &sQ1[lr1][0].x + comp;
    const float* p2 = &sQ2[lr2][0].x + comp;

    const float w1 = 256.0f * __ldg(&win[1023 - j]);
    const float w2 = 256.0f * __ldg(&win[767 - j]);
    const float w3 = 256.0f * __ldg(&win[511 - j]);
    const float w4 = 256.0f * __ldg(&win[255 - j]);

    const int dt0 = th * 16;
    float* ob = out + ((size_t)b * T_OUT + t0) * 256 + j;
#pragma unroll
    for (int q = 0; q < 16; q++) {
        int dt = dt0 + q;
        if (t0 + dt >= T_OUT) break;
        float v = w1 * p1[(dt + 3) * 2]
                + w2 * p2[(dt + 2) * 2]
                + w3 * p1[(dt + 1) * 2]
                + w4 * p2[dt * 2];
        ob[(size_t)dt * 256] = v;
    }
}

// ---------------------------------------------------------------------------
extern "C" void kernel_launch(void* const* d_in, const int* in_sizes, int n_in,
                              void* d_out, int out_size) {
    const float* in  = (const float*)d_in[0];   // (8, 514, 4000) f32
    const float* win = (const float*)d_in[1];   // (1024,) f32
    float* out = (float*)d_out;                 // (8, 3999*256) f32

    fft_kernel<<<2000, 256>>>(in);

    dim3 gE(125, 2, NB);
    epilogue_kernel<<<gE, 256>>>(win, out);
}

// round 9
// speedup vs baseline: 2.3385x; 1.4101x over previous
#include <cuda_runtime.h>
#include <math.h>

#define NB    8
#define D_IN  514
#define T_IN  4000
#define T_OUT 3999
#define NOUT  13                 // output columns per block
#define ST    17                 // plane row stride (floats), odd
#define PLOFF (256 * ST + 16)    // Ai offset: +16 banks vs Ar -> epilogue conflict-free

// ---------------------------------------------------------------------------
// 16-pt complex DFT, e^{+} kernel, in place, radix-4 x 2, compile-time W16.
// ---------------------------------------------------------------------------
__device__ __forceinline__ void dft16(float* xr, float* xi) {
    const float W16R[16] = { 1.0f,  0.923879533f,  0.707106781f,  0.382683432f,
                             0.0f, -0.382683432f, -0.707106781f, -0.923879533f,
                            -1.0f, -0.923879533f, -0.707106781f, -0.382683432f,
                             0.0f,  0.382683432f,  0.707106781f,  0.923879533f };
    const float W16I[16] = { 0.0f,  0.382683432f,  0.707106781f,  0.923879533f,
                             1.0f,  0.923879533f,  0.707106781f,  0.382683432f,
                             0.0f, -0.382683432f, -0.707106781f, -0.923879533f,
                            -1.0f, -0.923879533f, -0.707106781f, -0.382683432f };
    float qr[16], qi[16];
#pragma unroll
    for (int b = 0; b < 4; b++) {
        float a0r = xr[b],      a0i = xi[b];
        float a1r = xr[b + 4],  a1i = xi[b + 4];
        float a2r = xr[b + 8],  a2i = xi[b + 8];
        float a3r = xr[b + 12], a3i = xi[b + 12];
        float t0r = a0r + a2r, t0i = a0i + a2i;
        float t1r = a0r - a2r, t1i = a0i - a2i;
        float t2r = a1r + a3r, t2i = a1i + a3i;
        float t3r = a1r - a3r, t3i = a1i - a3i;
        float p0r = t0r + t2r, p0i = t0i + t2i;
        float p1r = t1r - t3i, p1i = t1i + t3r;   // + i*t3
        float p2r = t0r - t2r, p2i = t0i - t2i;
        float p3r = t1r + t3i, p3i = t1i - t3r;   // - i*t3
        qr[b] = p0r;  qi[b] = p0i;
#pragma unroll
        for (int j = 1; j < 4; j++) {
            float pr = (j == 1) ? p1r : (j == 2) ? p2r : p3r;
            float pi = (j == 1) ? p1i : (j == 2) ? p2i : p3i;
            float wr = W16R[(b * j) & 15], wi = W16I[(b * j) & 15];
            qr[4 * j + b] = pr * wr - pi * wi;
            qi[4 * j + b] = pr * wi + pi * wr;
        }
    }
#pragma unroll
    for (int j = 0; j < 4; j++) {
        float b0r = qr[4 * j],     b0i = qi[4 * j];
        float b1r = qr[4 * j + 1], b1i = qi[4 * j + 1];
        float b2r = qr[4 * j + 2], b2i = qi[4 * j + 2];
        float b3r = qr[4 * j + 3], b3i = qi[4 * j + 3];
        float t0r = b0r + b2r, t0i = b0i + b2i;
        float t1r = b0r - b2r, t1i = b0i - b2i;
        float t2r = b1r + b3r, t2i = b1i + b3i;
        float t3r = b1r - b3r, t3i = b1i - b3i;
        xr[j]      = t0r + t2r;  xi[j]      = t0i + t2i;
        xr[j + 4]  = t1r - t3i;  xi[j + 4]  = t1i + t3r;
        xr[j + 8]  = t0r - t2r;  xi[j + 8]  = t0i - t2i;
        xr[j + 12] = t1r + t3i;  xi[j + 12] = t1i - t3r;
    }
}

// ---------------------------------------------------------------------------
// Fused: conj-sym pack -> 256-pt register FFT (16x16 CT, one smem exchange)
// -> in-smem windowed overlap-add -> direct coalesced output store.
// Block: 16 FFT columns (3 halo), 13 output columns. 256 threads.
// ---------------------------------------------------------------------------
__global__ __launch_bounds__(256, 3) void fused_kernel(const float* __restrict__ in,
                                                       const float* __restrict__ win,
                                                       float* __restrict__ out) {
    __shared__ float sm[PLOFF + 256 * ST];
    float* Ar = sm;
    float* Ai = sm + PLOFF;

    const int tid = threadIdx.x;
    const int c   = tid & 15;
    const int lk  = tid >> 4;
    const int b   = blockIdx.y;
    const int t0  = blockIdx.x * NOUT;
    // FFT column cc covers global t = t0 - 3 + cc, cc in [0,16)
    const float* base = in + (size_t)b * D_IN * T_IN + t0 - 3;

    // ---- Build G[k] into planes (zero out-of-range columns) ----
#pragma unroll
    for (int it = 0; it < 9; it++) {
        int idx = tid + it * 256;
        if (idx >= 129 * 16) break;
        int kp = idx >> 4;
        int cc = idx & 15;
        int gt = t0 - 3 + cc;
        bool v = (gt >= 0) && (gt < T_IN);
        if (kp == 0) {
            float r0 = v ? base[cc] : 0.0f;
            Ar[cc] = r0;
            Ai[cc] = r0;
        } else if (kp == 128) {
            float r = v ? base[(size_t)128 * T_IN + cc] : 0.0f;
            float m = v ? base[(size_t)385 * T_IN + cc] : 0.0f;   // 257+128
            Ar[128 * ST + cc] = 2.0f * r;
            Ai[128 * ST + cc] = 2.0f * m;
        } else {
            float rk = 0.0f, mk = 0.0f, rp = 0.0f, mp = 0.0f;
            if (v) {
                rk = base[(size_t)kp * T_IN + cc];
                mk = base[(size_t)(257 + kp) * T_IN + cc];
                rp = base[(size_t)(256 - kp) * T_IN + cc];
                mp = base[(size_t)(513 - kp) * T_IN + cc];
            }
            float Er = rk + rp, Ei = mp - mk;
            float Dr = rk - rp, Di = -(mk + mp);
            float wr = cospif(kp / 256.0f), wi = sinpif(kp / 256.0f);
            float Or = Dr * wr - Di * wi;
            float Oi = Dr * wi + Di * wr;
            Ar[kp * ST + cc]         = Er - Oi;
            Ai[kp * ST + cc]         = Ei + Or;
            Ar[(256 - kp) * ST + cc] = Er + Oi;
            Ai[(256 - kp) * ST + cc] = Or - Ei;
        }
    }
    __syncthreads();

    float xr[16], xi[16];

    // ---- Phase 1: thread (c, n2=lk): X[a] = G[16a+n2], DFT over a ----
#pragma unroll
    for (int a = 0; a < 16; a++) {
        int r = (16 * a + lk) * ST + c;
        xr[a] = Ar[r];
        xi[a] = Ai[r];
    }
    dft16(xr, xi);

    // ---- Mid twiddle: F[k1] *= W256^{+n2*k1} ----
    {
        float bwr = cospif(lk / 128.0f), bwi = sinpif(lk / 128.0f);
        float wr = bwr, wi = bwi;
#pragma unroll
        for (int k1 = 1; k1 < 16; k1++) {
            float fr = xr[k1], fi = xi[k1];
            xr[k1] = fr * wr - fi * wi;
            xi[k1] = fr * wi + fi * wr;
            float nwr = wr * bwr - wi * bwi;
            float nwi = wr * bwi + wi * bwr;
            wr = nwr; wi = nwi;
        }
    }
    __syncthreads();

    // ---- Exchange: H[n2][k1] at row 16*k1 + n2 ----
#pragma unroll
    for (int k1 = 0; k1 < 16; k1++) {
        int r = (16 * k1 + lk) * ST + c;
        Ar[r] = xr[k1];
        Ai[r] = xi[k1];
    }
    __syncthreads();

    // ---- Phase 2: thread (c, k1=lk): Y[n2] = H[n2][k1], DFT over n2 ----
#pragma unroll
    for (int n2 = 0; n2 < 16; n2++) {
        int r = (16 * lk + n2) * ST + c;
        xr[n2] = Ar[r];
        xi[n2] = Ai[r];
    }
    dft16(xr, xi);
    __syncthreads();    // all phase-2 reads done before overwrite

    // ---- Store z[q] back to planes at row q (q = lk + 16*k2):
    //      Ar row q = s[2q], Ai row q = s[2q+1] ----
#pragma unroll
    for (int k2 = 0; k2 < 16; k2++) {
        int r = (lk + 16 * k2) * ST + c;
        Ar[r] = xr[k2];
        Ai[r] = xi[k2];
    }
    __syncthreads();

    // ---- Epilogue: out[b,t0+dt,j] = 256*( win[1023-j]*S[511-j][cc=dt+3]
    //        + win[767-j]*S[255-j][dt+2] + win[511-j]*S[511-j][dt+1]
    //        + win[255-j]*S[255-j][dt] ),  S[n] -> plane(n&1), row n>>1 ----
    {
        const int j  = tid;
        const int n1 = 511 - j;
        const int r1 = (n1 >> 1) * ST;
        const int r2 = ((255 - j) >> 1) * ST;
        const float* pl = (n1 & 1) ? Ai : Ar;
        const float w1 = 256.0f * __ldg(&win[1023 - j]);
        const float w2 = 256.0f * __ldg(&win[767 - j]);
        const float w3 = 256.0f * __ldg(&win[511 - j]);
        const float w4 = 256.0f * __ldg(&win[255 - j]);

        float* ob = out + ((size_t)b * T_OUT + t0) * 256 + j;
#pragma unroll
        for (int dt = 0; dt < NOUT; dt++) {
            if (t0 + dt >= T_OUT) break;
            float v = w1 * pl[r1 + dt + 3]
                    + w2 * pl[r2 + dt + 2]
                    + w3 * pl[r1 + dt + 1]
                    + w4 * pl[r2 + dt];
            ob[(size_t)dt * 256] = v;
        }
    }
}

// ---------------------------------------------------------------------------
extern "C" void kernel_launch(void* const* d_in, const int* in_sizes, int n_in,
                              void* d_out, int out_size) {
    const float* in  = (const float*)d_in[0];   // (8, 514, 4000) f32
    const float* win = (const float*)d_in[1];   // (1024,) f32
    float* out = (float*)d_out;                 // (8, 3999*256) f32

    dim3 g((T_OUT + NOUT - 1) / NOUT, NB);      // (308, 8)
    fused_kernel<<<g, 256>>>(in, win, out);
}

// round 10
// speedup vs baseline: 2.4485x; 1.0471x over previous
#include <cuda_runtime.h>
#include <math.h>

#define NB    8
#define D_IN  514
#define T_IN  4000
#define T_OUT 3999
#define NOUT  13                 // output columns per block
#define ST    17                 // plane row stride (in float2), odd

// ---------------------------------------------------------------------------
// 16-pt complex DFT, e^{+} kernel, in place, radix-4 x 2, compile-time W16.
// ---------------------------------------------------------------------------
__device__ __forceinline__ void dft16(float* xr, float* xi) {
    const float W16R[16] = { 1.0f,  0.923879533f,  0.707106781f,  0.382683432f,
                             0.0f, -0.382683432f, -0.707106781f, -0.923879533f,
                            -1.0f, -0.923879533f, -0.707106781f, -0.382683432f,
                             0.0f,  0.382683432f,  0.707106781f,  0.923879533f };
    const float W16I[16] = { 0.0f,  0.382683432f,  0.707106781f,  0.923879533f,
                             1.0f,  0.923879533f,  0.707106781f,  0.382683432f,
                             0.0f, -0.382683432f, -0.707106781f, -0.923879533f,
                            -1.0f, -0.923879533f, -0.707106781f, -0.382683432f };
    float qr[16], qi[16];
#pragma unroll
    for (int b = 0; b < 4; b++) {
        float a0r = xr[b],      a0i = xi[b];
        float a1r = xr[b + 4],  a1i = xi[b + 4];
        float a2r = xr[b + 8],  a2i = xi[b + 8];
        float a3r = xr[b + 12], a3i = xi[b + 12];
        float t0r = a0r + a2r, t0i = a0i + a2i;
        float t1r = a0r - a2r, t1i = a0i - a2i;
        float t2r = a1r + a3r, t2i = a1i + a3i;
        float t3r = a1r - a3r, t3i = a1i - a3i;
        float p0r = t0r + t2r, p0i = t0i + t2i;
        float p1r = t1r - t3i, p1i = t1i + t3r;   // + i*t3
        float p2r = t0r - t2r, p2i = t0i - t2i;
        float p3r = t1r + t3i, p3i = t1i - t3r;   // - i*t3
        qr[b] = p0r;  qi[b] = p0i;
#pragma unroll
        for (int j = 1; j < 4; j++) {
            float pr = (j == 1) ? p1r : (j == 2) ? p2r : p3r;
            float pi = (j == 1) ? p1i : (j == 2) ? p2i : p3i;
            float wr = W16R[(b * j) & 15], wi = W16I[(b * j) & 15];
            qr[4 * j + b] = pr * wr - pi * wi;
            qi[4 * j + b] = pr * wi + pi * wr;
        }
    }
#pragma unroll
    for (int j = 0; j < 4; j++) {
        float b0r = qr[4 * j],     b0i = qi[4 * j];
        float b1r = qr[4 * j + 1], b1i = qi[4 * j + 1];
        float b2r = qr[4 * j + 2], b2i = qi[4 * j + 2];
        float b3r = qr[4 * j + 3], b3i = qi[4 * j + 3];
        float t0r = b0r + b2r, t0i = b0i + b2i;
        float t1r = b0r - b2r, t1i = b0i - b2i;
        float t2r = b1r + b3r, t2i = b1i + b3i;
        float t3r = b1r - b3r, t3i = b1i - b3i;
        xr[j]      = t0r + t2r;  xi[j]      = t0i + t2i;
        xr[j + 4]  = t1r - t3i;  xi[j + 4]  = t1i + t3r;
        xr[j + 8]  = t0r - t2r;  xi[j + 8]  = t0i - t2i;
        xr[j + 12] = t1r + t3i;  xi[j + 12] = t1i - t3r;
    }
}

// ---------------------------------------------------------------------------
// Fused: conj-sym pack -> 256-pt register FFT (16x16 CT) -> windowed OLA.
// Interleaved float2 planes (vector LDS/STS), build-twiddle smem table,
// rolling 4-tap epilogue. Block: 16 FFT cols (3 halo), 13 outputs, 256 thr.
// ---------------------------------------------------------------------------
__global__ __launch_bounds__(256, 3) void fused_kernel(const float* __restrict__ in,
                                                       const float* __restrict__ win,
                                                       float* __restrict__ out) {
    __shared__ float2 A[256 * ST];     // (re, im) interleaved, row stride 17
    __shared__ float2 tw[128];         // e^{+pi i k/256}, k = 1..127 used

    const int tid = threadIdx.x;
    const int c   = tid & 15;
    const int lk  = tid >> 4;
    const int b   = blockIdx.y;
    const int t0  = blockIdx.x * NOUT;
    const float* base = in + (size_t)b * D_IN * T_IN + t0 - 3;

    // Epilogue window weights (hoisted: independent of FFT phases)
    const int j  = tid;
    const float w1 = 256.0f * __ldg(&win[1023 - j]);
    const float w2 = 256.0f * __ldg(&win[767 - j]);
    const float w3 = 256.0f * __ldg(&win[511 - j]);
    const float w4 = 256.0f * __ldg(&win[255 - j]);

    // ---- Twiddle table for the build phase ----
    if (tid < 128)
        tw[tid] = make_float2(cospif(tid / 256.0f), sinpif(tid / 256.0f));
    __syncthreads();

    // ---- Build G[k] into interleaved plane (zero out-of-range columns) ----
#pragma unroll
    for (int it = 0; it < 9; it++) {
        int idx = tid + it * 256;
        if (idx >= 129 * 16) break;
        int kp = idx >> 4;
        int cc = idx & 15;
        int gt = t0 - 3 + cc;
        bool v = (gt >= 0) && (gt < T_IN);
        if (kp == 0) {
            float r0 = v ? base[cc] : 0.0f;
            A[cc] = make_float2(r0, r0);
        } else if (kp == 128) {
            float r = v ? base[(size_t)128 * T_IN + cc] : 0.0f;
            float m = v ? base[(size_t)385 * T_IN + cc] : 0.0f;   // 257+128
            A[128 * ST + cc] = make_float2(2.0f * r, 2.0f * m);
        } else {
            float rk = 0.0f, mk = 0.0f, rp = 0.0f, mp = 0.0f;
            if (v) {
                rk = base[(size_t)kp * T_IN + cc];
                mk = base[(size_t)(257 + kp) * T_IN + cc];
                rp = base[(size_t)(256 - kp) * T_IN + cc];
                mp = base[(size_t)(513 - kp) * T_IN + cc];
            }
            float Er = rk + rp, Ei = mp - mk;
            float Dr = rk - rp, Di = -(mk + mp);
            float2 w = tw[kp];
            float Or = Dr * w.x - Di * w.y;
            float Oi = Dr * w.y + Di * w.x;
            A[kp * ST + cc]         = make_float2(Er - Oi, Ei + Or);
            A[(256 - kp) * ST + cc] = make_float2(Er + Oi, Or - Ei);
        }
    }
    __syncthreads();

    float xr[16], xi[16];

    // ---- Phase 1: thread (c, n2=lk): X[a] = G[16a+n2], DFT over a ----
#pragma unroll
    for (int a = 0; a < 16; a++) {
        float2 v = A[(16 * a + lk) * ST + c];
        xr[a] = v.x;
        xi[a] = v.y;
    }
    dft16(xr, xi);

    // ---- Mid twiddle: F[k1] *= W256^{+n2*k1} ----
    {
        float bwr = cospif(lk / 128.0f), bwi = sinpif(lk / 128.0f);
        float wr = bwr, wi = bwi;
#pragma unroll
        for (int k1 = 1; k1 < 16; k1++) {
            float fr = xr[k1], fi = xi[k1];
            xr[k1] = fr * wr - fi * wi;
            xi[k1] = fr * wi + fi * wr;
            float nwr = wr * bwr - wi * bwi;
            float nwi = wr * bwi + wi * bwr;
            wr = nwr; wi = nwi;
        }
    }
    __syncthreads();

    // ---- Exchange: H[n2][k1] at row 16*k1 + n2 ----
#pragma unroll
    for (int k1 = 0; k1 < 16; k1++)
        A[(16 * k1 + lk) * ST + c] = make_float2(xr[k1], xi[k1]);
    __syncthreads();

    // ---- Phase 2: thread (c, k1=lk): Y[n2] = H[n2][k1], DFT over n2 ----
#pragma unroll
    for (int n2 = 0; n2 < 16; n2++) {
        float2 v = A[(16 * lk + n2) * ST + c];
        xr[n2] = v.x;
        xi[n2] = v.y;
    }
    dft16(xr, xi);
    __syncthreads();    // all phase-2 reads done before overwrite

    // ---- Store z[q] at row q (q = lk + 16*k2): (s[2q], s[2q+1]) ----
#pragma unroll
    for (int k2 = 0; k2 < 16; k2++)
        A[(lk + 16 * k2) * ST + c] = make_float2(xr[k2], xi[k2]);
    __syncthreads();

    // ---- Epilogue: out[b,t0+dt,j] = w1*S1[dt+3] + w2*S2[dt+2]
    //                               + w3*S1[dt+1] + w4*S2[dt]
    //      S1 = S[511-j], S2 = S[255-j]; S[n] -> float comp (n&1) of row n>>1.
    //      Rolling window: 2 new LDS per dt instead of 4. ----
    {
        const float* Af = (const float*)A;
        const int n1 = 511 - j;
        const int f1 = ((n1 >> 1) * ST) * 2 + (n1 & 1);          // float index base
        const int f2 = (((255 - j) >> 1) * ST) * 2 + (n1 & 1);   // same parity
        float p1a = Af[f1 + 1 * 2];   // S1[1]
        float p1b = Af[f1 + 2 * 2];   // S1[2]
        float p2a = Af[f2 + 0 * 2];   // S2[0]
        float p2b = Af[f2 + 1 * 2];   // S2[1]

        float* ob = out + ((size_t)b * T_OUT + t0) * 256 + j;
#pragma unroll
        for (int dt = 0; dt < NOUT; dt++) {
            if (t0 + dt >= T_OUT) break;
            float n1v = Af[f1 + (dt + 3) * 2];    // S1[dt+3]
            float n2v = Af[f2 + (dt + 2) * 2];    // S2[dt+2]
            float v = w1 * n1v + w2 * n2v + w3 * p1a + w4 * p2a;
            ob[(size_t)dt * 256] = v;
            p1a = p1b; p1b = n1v;
            p2a = p2b; p2b = n2v;
        }
    }
}

// ---------------------------------------------------------------------------
extern "C" void kernel_launch(void* const* d_in, const int* in_sizes, int n_in,
                              void* d_out, int out_size) {
    const float* in  = (const float*)d_in[0];   // (8, 514, 4000) f32
    const float* win = (const float*)d_in[1];   // (1024,) f32
    float* out = (float*)d_out;                 // (8, 3999*256) f32

    dim3 g((T_OUT + NOUT - 1) / NOUT, NB);      // (308, 8)
    fused_kernel<<<g, 256>>>(in, win, out);
}

// round 11
// speedup vs baseline: 2.7340x; 1.1166x over previous
#include <cuda_runtime.h>
#include <math.h>

#define NB    8
#define D_IN  514
#define T_IN  4000
#define T_OUT 3999
#define NOUT  13                 // output columns per block
#define ST    17                 // plane row stride (in float2), odd

// Slot permutation left by the in-place DFT16: F[k] lives at slot sigma(k).
#define SIGMA(k) ((((k) & 3) << 2) | ((k) >> 2))

// ---------------------------------------------------------------------------
// 16-pt complex DFT, e^{+} kernel, IN PLACE (no scratch array).
// Output permuted: F[j+4m] stored at slot 4j+m, i.e. F[k] at SIGMA(k).
// ---------------------------------------------------------------------------
__device__ __forceinline__ void dft16_ip(float* xr, float* xi) {
    const float W16R[16] = { 1.0f,  0.923879533f,  0.707106781f,  0.382683432f,
                             0.0f, -0.382683432f, -0.707106781f, -0.923879533f,
                            -1.0f, -0.923879533f, -0.707106781f, -0.382683432f,
                             0.0f,  0.382683432f,  0.707106781f,  0.923879533f };
    const float W16I[16] = { 0.0f,  0.382683432f,  0.707106781f,  0.923879533f,
                             1.0f,  0.923879533f,  0.707106781f,  0.382683432f,
                             0.0f, -0.382683432f, -0.707106781f, -0.923879533f,
                            -1.0f, -0.923879533f, -0.707106781f, -0.382683432f };
    // Stage A (per b): 4-pt e+ DFT over a of x[b+4a], twiddle by W16^{bj},
    // store Q_b[j] back IN PLACE at slot b+4j (same slot set just consumed).
#pragma unroll
    for (int b = 0; b < 4; b++) {
        float a0r = xr[b],      a0i = xi[b];
        float a1r = xr[b + 4],  a1i = xi[b + 4];
        float a2r = xr[b + 8],  a2i = xi[b + 8];
        float a3r = xr[b + 12], a3i = xi[b + 12];
        float t0r = a0r + a2r, t0i = a0i + a2i;
        float t1r = a0r - a2r, t1i = a0i - a2i;
        float t2r = a1r + a3r, t2i = a1i + a3i;
        float t3r = a1r - a3r, t3i = a1i - a3i;
        float p0r = t0r + t2r, p0i = t0i + t2i;
        float p1r = t1r - t3i, p1i = t1i + t3r;   // + i*t3
        float p2r = t0r - t2r, p2i = t0i - t2i;
        float p3r = t1r + t3i, p3i = t1i - t3r;   // - i*t3
        xr[b] = p0r;  xi[b] = p0i;                // j=0: W^0
#pragma unroll
        for (int jj = 1; jj < 4; jj++) {
            float pr = (jj == 1) ? p1r : (jj == 2) ? p2r : p3r;
            float pi = (jj == 1) ? p1i : (jj == 2) ? p2i : p3i;
            float wr = W16R[(b * jj) & 15], wi = W16I[(b * jj) & 15];
            xr[b + 4 * jj] = pr * wr - pi * wi;
            xi[b + 4 * jj] = pr * wi + pi * wr;
        }
    }
    // Stage B (per j): 4-pt e+ DFT over b of Q at slots 4j..4j+3 (contiguous),
    // write F[j+4m] IN PLACE at slot 4j+m.
#pragma unroll
    for (int jj = 0; jj < 4; jj++) {
        float b0r = xr[4 * jj],     b0i = xi[4 * jj];
        float b1r = xr[4 * jj + 1], b1i = xi[4 * jj + 1];
        float b2r = xr[4 * jj + 2], b2i = xi[4 * jj + 2];
        float b3r = xr[4 * jj + 3], b3i = xi[4 * jj + 3];
        float t0r = b0r + b2r, t0i = b0i + b2i;
        float t1r = b0r - b2r, t1i = b0i - b2i;
        float t2r = b1r + b3r, t2i = b1i + b3i;
        float t3r = b1r - b3r, t3i = b1i - b3i;
        xr[4 * jj]     = t0r + t2r;  xi[4 * jj]     = t0i + t2i;   // m=0
        xr[4 * jj + 1] = t1r - t3i;  xi[4 * jj + 1] = t1i + t3r;   // m=1: +i*t3
        xr[4 * jj + 2] = t0r - t2r;  xi[4 * jj + 2] = t0i - t2i;   // m=2
        xr[4 * jj + 3] = t1r + t3i;  xi[4 * jj + 3] = t1i - t3r;   // m=3: -i*t3
    }
}

// ---------------------------------------------------------------------------
// Fused: conj-sym pack -> 256-pt register FFT (16x16 CT, in-place DFT16s)
// -> windowed overlap-add. Block: 16 FFT cols (3 halo), 13 outputs, 256 thr.
// ---------------------------------------------------------------------------
__global__ __launch_bounds__(256, 4) void fused_kernel(const float* __restrict__ in,
                                                       const float* __restrict__ win,
                                                       float* __restrict__ out) {
    __shared__ float2 A[256 * ST];     // (re, im) interleaved, row stride 17
    __shared__ float2 tw[128];         // e^{+pi i k/256}

    const int tid = threadIdx.x;
    const int c   = tid & 15;
    const int lk  = tid >> 4;
    const int b   = blockIdx.y;
    const int t0  = blockIdx.x * NOUT;
    const float* base = in + (size_t)b * D_IN * T_IN + t0 - 3;

    // ---- Twiddle table for the build phase ----
    if (tid < 128)
        tw[tid] = make_float2(cospif(tid / 256.0f), sinpif(tid / 256.0f));
    __syncthreads();

    // ---- Build G[k] into interleaved plane (zero out-of-range columns) ----
#pragma unroll
    for (int it = 0; it < 9; it++) {
        int idx = tid + it * 256;
        if (idx >= 129 * 16) break;
        int kp = idx >> 4;
        int cc = idx & 15;
        int gt = t0 - 3 + cc;
        bool v = (gt >= 0) && (gt < T_IN);
        if (kp == 0) {
            float r0 = v ? base[cc] : 0.0f;
            A[cc] = make_float2(r0, r0);
        } else if (kp == 128) {
            float r = v ? base[(size_t)128 * T_IN + cc] : 0.0f;
            float m = v ? base[(size_t)385 * T_IN + cc] : 0.0f;   // 257+128
            A[128 * ST + cc] = make_float2(2.0f * r, 2.0f * m);
        } else {
            float rk = 0.0f, mk = 0.0f, rp = 0.0f, mp = 0.0f;
            if (v) {
                rk = base[(size_t)kp * T_IN + cc];
                mk = base[(size_t)(257 + kp) * T_IN + cc];
                rp = base[(size_t)(256 - kp) * T_IN + cc];
                mp = base[(size_t)(513 - kp) * T_IN + cc];
            }
            float Er = rk + rp, Ei = mp - mk;
            float Dr = rk - rp, Di = -(mk + mp);
            float2 w = tw[kp];
            float Or = Dr * w.x - Di * w.y;
            float Oi = Dr * w.y + Di * w.x;
            A[kp * ST + cc]         = make_float2(Er - Oi, Ei + Or);
            A[(256 - kp) * ST + cc] = make_float2(Er + Oi, Or - Ei);
        }
    }
    __syncthreads();

    float xr[16], xi[16];

    // ---- Phase 1: thread (c, n2=lk): X[a] = G[16a+n2], DFT over a ----
#pragma unroll
    for (int a = 0; a < 16; a++) {
        float2 v = A[(16 * a + lk) * ST + c];
        xr[a] = v.x;
        xi[a] = v.y;
    }
    dft16_ip(xr, xi);     // F1[k1] now at slot SIGMA(k1)

    // ---- Mid twiddle: F1[k1] *= W256^{+n2*k1}, k1 sequential, slot remap ----
    {
        float bwr = cospif(lk / 128.0f), bwi = sinpif(lk / 128.0f);
        float wr = bwr, wi = bwi;
#pragma unroll
        for (int k1 = 1; k1 < 16; k1++) {
            int s = SIGMA(k1);
            float fr = xr[s], fi = xi[s];
            xr[s] = fr * wr - fi * wi;
            xi[s] = fr * wi + fi * wr;
            float nwr = wr * bwr - wi * bwi;
            float nwi = wr * bwi + wi * bwr;
            wr = nwr; wi = nwi;
        }
    }
    __syncthreads();

    // ---- Exchange: H[n2][k1] at row 16*k1 + n2 (read slot SIGMA(k1)) ----
#pragma unroll
    for (int k1 = 0; k1 < 16; k1++) {
        int s = SIGMA(k1);
        A[(16 * k1 + lk) * ST + c] = make_float2(xr[s], xi[s]);
    }
    __syncthreads();

    // ---- Phase 2: thread (c, k1=lk): Y[n2] = H[n2][k1], DFT over n2 ----
#pragma unroll
    for (int n2 = 0; n2 < 16; n2++) {
        float2 v = A[(16 * lk + n2) * ST + c];
        xr[n2] = v.x;
        xi[n2] = v.y;
    }
    dft16_ip(xr, xi);     // F2[k2] at slot SIGMA(k2)
    __syncthreads();      // all phase-2 reads done before overwrite

    // ---- Store z[q] at row q = lk + 16*k2 (read slot SIGMA(k2)) ----
#pragma unroll
    for (int k2 = 0; k2 < 16; k2++) {
        int s = SIGMA(k2);
        A[(lk + 16 * k2) * ST + c] = make_float2(xr[s], xi[s]);
    }
    __syncthreads();

    // ---- Epilogue: out[b,t0+dt,j] = w1*S1[dt+3] + w2*S2[dt+2]
    //                               + w3*S1[dt+1] + w4*S2[dt]
    //      S1 = S[511-j], S2 = S[255-j]; S[n] -> float comp (n&1) of row n>>1.
    //      Rolling window: 2 new LDS per dt. ----
    {
        const int j  = tid;
        const float w1 = 256.0f * __ldg(&win[1023 - j]);
        const float w2 = 256.0f * __ldg(&win[767 - j]);
        const float w3 = 256.0f * __ldg(&win[511 - j]);
        const float w4 = 256.0f * __ldg(&win[255 - j]);

        const float* Af = (const float*)A;
        const int n1 = 511 - j;
        const int f1 = ((n1 >> 1) * ST) * 2 + (n1 & 1);
        const int f2 = (((255 - j) >> 1) * ST) * 2 + (n1 & 1);
        float p1a = Af[f1 + 1 * 2];
        float p1b = Af[f1 + 2 * 2];
        float p2a = Af[f2 + 0 * 2];
        float p2b = Af[f2 + 1 * 2];

        float* ob = out + ((size_t)b * T_OUT + t0) * 256 + j;
#pragma unroll
        for (int dt = 0; dt < NOUT; dt++) {
            if (t0 + dt >= T_OUT) break;
            float n1v = Af[f1 + (dt + 3) * 2];
            float n2v = Af[f2 + (dt + 2) * 2];
            float v = w1 * n1v + w2 * n2v + w3 * p1a + w4 * p2a;
            ob[(size_t)dt * 256] = v;
            p1a = p1b; p1b = n1v;
            p2a = p2b; p2b = n2v;
        }
    }
}

// ---------------------------------------------------------------------------
extern "C" void kernel_launch(void* const* d_in, const int* in_sizes, int n_in,
                              void* d_out, int out_size) {
    const float* in  = (const float*)d_in[0];   // (8, 514, 4000) f32
    const float* win = (const float*)d_in[1];   // (1024,) f32
    float* out = (float*)d_out;                 // (8, 3999*256) f32

    dim3 g((T_OUT + NOUT - 1) / NOUT, NB);      // (308, 8)
    fused_kernel<<<g, 256>>>(in, win, out);
}

// round 12
// speedup vs baseline: 2.9083x; 1.0638x over previous
#include <cuda_runtime.h>
#include <math.h>

#define NB     8
#define D_IN   514
#define T_IN   4000
#define T_OUT  3999
#define NCOL   32                // FFT columns per block
#define NOUT   29                // output columns per block (3 halo)
#define ST     33                // plane row stride (in float2), odd
#define NTHR   512

// Slot permutation left by the in-place DFT16: F[k] lives at slot sigma(k).
#define SIGMA(k) ((((k) & 3) << 2) | ((k) >> 2))

// dynamic smem: A[256*ST] float2 | tw[128] float2 | tw2[256] float2
#define SM_A    0
#define SM_TW   (256 * ST)
#define SM_TW2  (256 * ST + 128)
#define SM_F2   (256 * ST + 128 + 256)
#define SMEM_BYTES (SM_F2 * 8)

// ---------------------------------------------------------------------------
// 16-pt complex DFT, e^{+} kernel, IN PLACE. Output at slot SIGMA(k).
// ---------------------------------------------------------------------------
__device__ __forceinline__ void dft16_ip(float* xr, float* xi) {
    const float W16R[16] = { 1.0f,  0.923879533f,  0.707106781f,  0.382683432f,
                             0.0f, -0.382683432f, -0.707106781f, -0.923879533f,
                            -1.0f, -0.923879533f, -0.707106781f, -0.382683432f,
                             0.0f,  0.382683432f,  0.707106781f,  0.923879533f };
    const float W16I[16] = { 0.0f,  0.382683432f,  0.707106781f,  0.923879533f,
                             1.0f,  0.923879533f,  0.707106781f,  0.382683432f,
                             0.0f, -0.382683432f, -0.707106781f, -0.923879533f,
                            -1.0f, -0.923879533f, -0.707106781f, -0.382683432f };
#pragma unroll
    for (int b = 0; b < 4; b++) {
        float a0r = xr[b],      a0i = xi[b];
        float a1r = xr[b + 4],  a1i = xi[b + 4];
        float a2r = xr[b + 8],  a2i = xi[b + 8];
        float a3r = xr[b + 12], a3i = xi[b + 12];
        float t0r = a0r + a2r, t0i = a0i + a2i;
        float t1r = a0r - a2r, t1i = a0i - a2i;
        float t2r = a1r + a3r, t2i = a1i + a3i;
        float t3r = a1r - a3r, t3i = a1i - a3i;
        float p0r = t0r + t2r, p0i = t0i + t2i;
        float p1r = t1r - t3i, p1i = t1i + t3r;   // + i*t3
        float p2r = t0r - t2r, p2i = t0i - t2i;
        float p3r = t1r + t3i, p3i = t1i - t3r;   // - i*t3
        xr[b] = p0r;  xi[b] = p0i;
#pragma unroll
        for (int jj = 1; jj < 4; jj++) {
            float pr = (jj == 1) ? p1r : (jj == 2) ? p2r : p3r;
            float pi = (jj == 1) ? p1i : (jj == 2) ? p2i : p3i;
            float wr = W16R[(b * jj) & 15], wi = W16I[(b * jj) & 15];
            xr[b + 4 * jj] = pr * wr - pi * wi;
            xi[b + 4 * jj] = pr * wi + pi * wr;
        }
    }
#pragma unroll
    for (int jj = 0; jj < 4; jj++) {
        float b0r = xr[4 * jj],     b0i = xi[4 * jj];
        float b1r = xr[4 * jj + 1], b1i = xi[4 * jj + 1];
        float b2r = xr[4 * jj + 2], b2i = xi[4 * jj + 2];
        float b3r = xr[4 * jj + 3], b3i = xi[4 * jj + 3];
        float t0r = b0r + b2r, t0i = b0i + b2i;
        float t1r = b0r - b2r, t1i = b0i - b2i;
        float t2r = b1r + b3r, t2i = b1i + b3i;
        float t3r = b1r - b3r, t3i = b1i - b3i;
        xr[4 * jj]     = t0r + t2r;  xi[4 * jj]     = t0i + t2i;
        xr[4 * jj + 1] = t1r - t3i;  xi[4 * jj + 1] = t1i + t3r;
        xr[4 * jj + 2] = t0r - t2r;  xi[4 * jj + 2] = t0i - t2i;
        xr[4 * jj + 3] = t1r + t3i;  xi[4 * jj + 3] = t1i - t3r;
    }
}

// ---------------------------------------------------------------------------
// Fused: conj-sym pack -> 256-pt register FFT (16x16 CT) -> windowed OLA.
// 512 threads, 32 FFT cols (3 halo), 29 outputs per block.
// ---------------------------------------------------------------------------
__global__ __launch_bounds__(NTHR, 2) void fused_kernel(const float* __restrict__ in,
                                                        const float* __restrict__ win,
                                                        float* __restrict__ out) {
    extern __shared__ float2 sm[];
    float2* A   = sm + SM_A;      // row stride ST (float2)
    float2* tw  = sm + SM_TW;     // e^{+pi i k/256}
    float2* tw2 = sm + SM_TW2;    // e^{+2pi i m/256}

    const int tid = threadIdx.x;
    const int c   = tid & 31;
    const int lk  = tid >> 5;                 // 0..15
    const int b   = blockIdx.y;
    const int t0  = blockIdx.x * NOUT;
    const float* base = in + (size_t)b * D_IN * T_IN + t0 - 3;

    if (tid < 128)
        tw[tid] = make_float2(cospif(tid / 256.0f), sinpif(tid / 256.0f));
    else if (tid < 384) {
        int m = tid - 128;
        tw2[m] = make_float2(cospif(m / 128.0f), sinpif(m / 128.0f));
    }
    __syncthreads();

    // ---- Build G[k] (zero out-of-range columns) ----
#pragma unroll
    for (int it = 0; it < 9; it++) {
        int idx = tid + it * NTHR;
        if (idx >= 129 * NCOL) break;
        int kp = idx >> 5;
        int cc = idx & 31;
        int gt = t0 - 3 + cc;
        bool v = (gt >= 0) && (gt < T_IN);
        if (kp == 0) {
            float r0 = v ? base[cc] : 0.0f;
            A[cc] = make_float2(r0, r0);
        } else if (kp == 128) {
            float r = v ? base[(size_t)128 * T_IN + cc] : 0.0f;
            float m = v ? base[(size_t)385 * T_IN + cc] : 0.0f;   // 257+128
            A[128 * ST + cc] = make_float2(2.0f * r, 2.0f * m);
        } else {
            float rk = 0.0f, mk = 0.0f, rp = 0.0f, mp = 0.0f;
            if (v) {
                rk = base[(size_t)kp * T_IN + cc];
                mk = base[(size_t)(257 + kp) * T_IN + cc];
                rp = base[(size_t)(256 - kp) * T_IN + cc];
                mp = base[(size_t)(513 - kp) * T_IN + cc];
            }
            float Er = rk + rp, Ei = mp - mk;
            float Dr = rk - rp, Di = -(mk + mp);
            float2 w = tw[kp];
            float Or = Dr * w.x - Di * w.y;
            float Oi = Dr * w.y + Di * w.x;
            A[kp * ST + cc]         = make_float2(Er - Oi, Ei + Or);
            A[(256 - kp) * ST + cc] = make_float2(Er + Oi, Or - Ei);
        }
    }
    __syncthreads();

    float xr[16], xi[16];

    // ---- Phase 1: thread (c, n2=lk): X[a] = G[16a+n2] ----
#pragma unroll
    for (int a = 0; a < 16; a++) {
        float2 v = A[(16 * a + lk) * ST + c];
        xr[a] = v.x;
        xi[a] = v.y;
    }
    dft16_ip(xr, xi);     // F1[k1] at slot SIGMA(k1)

    // ---- Mid twiddle from table: F1[k1] *= W256^{+n2*k1} (broadcast LDS) ----
#pragma unroll
    for (int k1 = 1; k1 < 16; k1++) {
        int s = SIGMA(k1);
        float2 w = tw2[lk * k1];          // lk*k1 <= 225 < 256
        float fr = xr[s], fi = xi[s];
        xr[s] = fr * w.x - fi * w.y;
        xi[s] = fr * w.y + fi * w.x;
    }
    __syncthreads();

    // ---- Exchange: H[n2][k1] at row 16*k1 + n2 ----
#pragma unroll
    for (int k1 = 0; k1 < 16; k1++) {
        int s = SIGMA(k1);
        A[(16 * k1 + lk) * ST + c] = make_float2(xr[s], xi[s]);
    }
    __syncthreads();

    // ---- Phase 2: thread (c, k1=lk): Y[n2] = H[n2][k1] ----
#pragma unroll
    for (int n2 = 0; n2 < 16; n2++) {
        float2 v = A[(16 * lk + n2) * ST + c];
        xr[n2] = v.x;
        xi[n2] = v.y;
    }
    dft16_ip(xr, xi);     // F2[k2] at slot SIGMA(k2)
    __syncthreads();

    // ---- Store z[q] at row q = lk + 16*k2 ----
#pragma unroll
    for (int k2 = 0; k2 < 16; k2++) {
        int s = SIGMA(k2);
        A[(lk + 16 * k2) * ST + c] = make_float2(xr[s], xi[s]);
    }
    __syncthreads();

    // ---- Epilogue: out[b,t0+dt,j] = w1*S1[dt+3] + w2*S2[dt+2]
    //                               + w3*S1[dt+1] + w4*S2[dt]
    //      512 thr = 256 j x 2 dt-halves. Rolling 4-tap window. ----
    {
        const int j   = tid & 255;
        const int th  = tid >> 8;
        const int dt0 = th * 15;          // th=0: dt 0..14, th=1: dt 15..28
        const float w1 = 256.0f * __ldg(&win[1023 - j]);
        const float w2 = 256.0f * __ldg(&win[767 - j]);
        const float w3 = 256.0f * __ldg(&win[511 - j]);
        const float w4 = 256.0f * __ldg(&win[255 - j]);

        const float* Af = (const float*)A;
        const int n1 = 511 - j;
        const int f1 = ((n1 >> 1) * ST) * 2 + (n1 & 1);
        const int f2 = (((255 - j) >> 1) * ST) * 2 + (n1 & 1);
        float p1a = Af[f1 + (dt0 + 1) * 2];
        float p1b = Af[f1 + (dt0 + 2) * 2];
        float p2a = Af[f2 + (dt0 + 0) * 2];
        float p2b = Af[f2 + (dt0 + 1) * 2];

        float* ob = out + ((size_t)b * T_OUT + t0) * 256 + j;
#pragma unroll
        for (int q = 0; q < 15; q++) {
            int dt = dt0 + q;
            if (dt >= NOUT || t0 + dt >= T_OUT) break;
            float n1v = Af[f1 + (dt + 3) * 2];
            float n2v = Af[f2 + (dt + 2) * 2];
            float v = w1 * n1v + w2 * n2v + w3 * p1a + w4 * p2a;
            ob[(size_t)dt * 256] = v;
            p1a = p1b; p1b = n1v;
            p2a = p2b; p2b = n2v;
        }
    }
}

// ---------------------------------------------------------------------------
extern "C" void kernel_launch(void* const* d_in, const int* in_sizes, int n_in,
                              void* d_out, int out_size) {
    const float* in  = (const float*)d_in[0];   // (8, 514, 4000) f32
    const float* win = (const float*)d_in[1];   // (1024,) f32
    float* out = (float*)d_out;                 // (8, 3999*256) f32

    cudaFuncSetAttribute(fused_kernel,
                         cudaFuncAttributeMaxDynamicSharedMemorySize, SMEM_BYTES);

    dim3 g((T_OUT + NOUT - 1) / NOUT, NB);      // (138, 8)
    fused_kernel<<<g, NTHR, SMEM_BYTES>>>(in, win, out);
}